// round 4
// baseline (speedup 1.0000x reference)
#include <cuda_runtime.h>
#include <math.h>
#include <stdint.h>

// Problem dims (fixed by reference)
#define BB   4
#define SS   2048
#define DM   1024          // d_model
#define DH   4096          // d_hidden
#define MROWS (BB*SS)      // 8192 tokens

// ---------------- static device scratch (no allocation allowed) ----------------
__device__ float  g_h[(size_t)MROWS * DH];        // GEMM1 output (fp32), 128 MB
__device__ int    g_xq[MROWS * (DM/4)];           // x int8 packed, 8 MB
__device__ int    g_gq[MROWS * (DH/4)];           // silu(conv) int8 packed, 32 MB
__device__ int    g_w1q[DH * (DM/4)];             // ternary w1 packed, 4 MB
__device__ int    g_w2q[DM * (DH/4)];             // ternary w2 packed, 4 MB
__device__ float  g_factx[MROWS];                 // per-token 1/scale for x
__device__ float  g_factg[MROWS];                 // per-token 1/scale for g
__device__ double g_part[512];                    // weight |.| partial sums
__device__ float  g_wstats[4];                    // [0]=scale1 [1]=1/scale1 [2]=scale2 [3]=1/scale2

// ---------------- helpers ----------------
__device__ __forceinline__ int pack4(int a, int b, int c, int d) {
    return (a & 0xFF) | ((b & 0xFF) << 8) | ((c & 0xFF) << 16) | ((d & 0xFF) << 24);
}
__device__ __forceinline__ int q8(float v, float s, int lo, int hi) {
    int q = (int)rintf(v * s);
    return min(hi, max(lo, q));
}

// ---------------- weight abs-mean: deterministic 2-stage fp64 reduction ----------------
__global__ void k_wabs_part(const float* __restrict__ w1, const float* __restrict__ w2) {
    // blocks 0..255 -> w1, 256..511 -> w2. Each block sums a fixed contiguous chunk.
    const float* w = (blockIdx.x < 256) ? w1 : w2;
    const int b = blockIdx.x & 255;
    const int n = DH * DM;            // 4M for both
    const int chunk = n / 256;        // 16384
    const int base = b * chunk;
    double s = 0.0;
    for (int j = threadIdx.x; j < chunk; j += 256) s += (double)fabsf(w[base + j]);
    __shared__ double sm[256];
    sm[threadIdx.x] = s;
    __syncthreads();
    for (int o = 128; o > 0; o >>= 1) {
        if (threadIdx.x < o) sm[threadIdx.x] += sm[threadIdx.x + o];
        __syncthreads();
    }
    if (threadIdx.x == 0) g_part[blockIdx.x] = sm[0];
}

__global__ void k_wabs_final() {
    const int w = blockIdx.x;  // 0 or 1
    __shared__ double sm[256];
    sm[threadIdx.x] = g_part[w * 256 + threadIdx.x];
    __syncthreads();
    for (int o = 128; o > 0; o >>= 1) {
        if (threadIdx.x < o) sm[threadIdx.x] += sm[threadIdx.x + o];
        __syncthreads();
    }
    if (threadIdx.x == 0) {
        float mean  = (float)(sm[0] / (double)(DH * DM));
        float clipd = fmaxf(mean, 1e-5f);
        float scale = 1.0f / clipd;           // matches reference fp32 formula
        g_wstats[2 * w]     = scale;
        g_wstats[2 * w + 1] = 1.0f / scale;   // per-element dequant factor (ref divides by scale)
    }
}

// ---------------- ternary-quantize weights (packed int8) ----------------
__global__ void k_quant_w(const float* __restrict__ w, int* __restrict__ q, int n4, int sidx) {
    const float scale = g_wstats[sidx];
    int i = blockIdx.x * blockDim.x + threadIdx.x;
    if (i < n4) {
        float4 v = reinterpret_cast<const float4*>(w)[i];
        q[i] = pack4(q8(v.x, scale, -1, 1), q8(v.y, scale, -1, 1),
                     q8(v.z, scale, -1, 1), q8(v.w, scale, -1, 1));
    }
}

// ---------------- per-token int8 quantize of x (one block per token) ----------------
__global__ void k_quant_x(const float* __restrict__ x) {
    const int row = blockIdx.x;
    const int t = threadIdx.x;
    float4 v = reinterpret_cast<const float4*>(x + (size_t)row * DM)[t];  // 256 threads * 4 = 1024
    float m = fmaxf(fmaxf(fabsf(v.x), fabsf(v.y)), fmaxf(fabsf(v.z), fabsf(v.w)));
    __shared__ float sm[256];
    sm[t] = m;
    __syncthreads();
    for (int o = 128; o > 0; o >>= 1) {
        if (t < o) sm[t] = fmaxf(sm[t], sm[t + o]);
        __syncthreads();
    }
    float mx = fmaxf(sm[0], 1e-5f);
    float scale = 127.0f / mx;
    g_xq[row * (DM/4) + t] = pack4(q8(v.x, scale, -128, 127), q8(v.y, scale, -128, 127),
                                   q8(v.z, scale, -128, 127), q8(v.w, scale, -128, 127));
    if (t == 0) g_factx[row] = 1.0f / scale;
}

// ---------------- int8 x ternary GEMM (dp4a, 128x128 tile, double-buffered) ----------------
// C[m,n] = (Σ_k A8[m,k]*B8[n,k]) * rowf[m] * ws
__global__ __launch_bounds__(256, 1)
void k_gemm(const int* __restrict__ A, const int* __restrict__ Bw,
            float* __restrict__ C, const float* __restrict__ rowf,
            const float* __restrict__ wsp, int N, int K4) {
    __shared__ int As[2][16][132];
    __shared__ int Bs[2][16][132];
    const int tid = threadIdx.x;
    const int tx = tid & 15;
    const int ty = tid >> 4;
    const int bm0 = blockIdx.y << 7;
    const int bn0 = blockIdx.x << 7;
    const int T = K4 >> 4;

    int aR[8], bR[8];
    int acc[8][8];
#pragma unroll
    for (int i = 0; i < 8; i++)
#pragma unroll
        for (int j = 0; j < 8; j++) acc[i][j] = 0;

    // prefetch tile 0 into registers
#pragma unroll
    for (int i = 0; i < 8; i++) {
        int r = ty + 16 * i;
        aR[i] = A[(size_t)(bm0 + r) * K4 + tx];
        bR[i] = Bw[(size_t)(bn0 + r) * K4 + tx];
    }

    for (int t = 0; t < T; t++) {
        const int buf = t & 1;
        // store current tile (transposed, padded -> conflict-light)
#pragma unroll
        for (int i = 0; i < 8; i++) {
            int r = ty + 16 * i;
            As[buf][tx][r] = aR[i];
            Bs[buf][tx][r] = bR[i];
        }
        __syncthreads();
        // prefetch next tile
        if (t + 1 < T) {
            const int k0 = (t + 1) << 4;
#pragma unroll
            for (int i = 0; i < 8; i++) {
                int r = ty + 16 * i;
                aR[i] = A[(size_t)(bm0 + r) * K4 + k0 + tx];
                bR[i] = Bw[(size_t)(bn0 + r) * K4 + k0 + tx];
            }
        }
        // compute on current buffer
#pragma unroll
        for (int k = 0; k < 16; k++) {
            int af[8], bf[8];
#pragma unroll
            for (int i = 0; i < 8; i++) af[i] = As[buf][k][ty + 16 * i];
#pragma unroll
            for (int j = 0; j < 8; j++) bf[j] = Bs[buf][k][tx + 16 * j];
#pragma unroll
            for (int i = 0; i < 8; i++)
#pragma unroll
                for (int j = 0; j < 8; j++)
                    acc[i][j] = __dp4a(af[i], bf[j], acc[i][j]);
        }
        __syncthreads();
    }

    const float ws = wsp[0];
#pragma unroll
    for (int i = 0; i < 8; i++) {
        const int r = bm0 + ty + 16 * i;
        const float f = rowf[r] * ws;
#pragma unroll
        for (int j = 0; j < 8; j++)
            C[(size_t)r * N + bn0 + tx + 16 * j] = (float)acc[i][j] * f;
    }
}

// ---------------- depthwise conv3 + bias + SiLU + per-token int8 quantize ----------------
// one block per token row; threads cover 4096 channels (16 consecutive each)
__global__ void k_conv(const float* __restrict__ cw, const float* __restrict__ cb) {
    const int row = blockIdx.x;
    const int s = row & (SS - 1);
    const int t = threadIdx.x;
    const float* h0 = g_h + (size_t)row * DH;
    const float* hm = h0 - DH;
    const float* hp = h0 + DH;
    const bool has_m = (s > 0);
    const bool has_p = (s < SS - 1);

    float g[16];
    float amax = 0.0f;
    const int cbase = t * 16;
#pragma unroll
    for (int k = 0; k < 4; k++) {
        const int c0 = cbase + k * 4;
        float4 a = has_m ? reinterpret_cast<const float4*>(hm + c0)[0] : make_float4(0.f, 0.f, 0.f, 0.f);
        float4 b = reinterpret_cast<const float4*>(h0 + c0)[0];
        float4 c = has_p ? reinterpret_cast<const float4*>(hp + c0)[0] : make_float4(0.f, 0.f, 0.f, 0.f);
        float av[4] = {a.x, a.y, a.z, a.w};
        float bv[4] = {b.x, b.y, b.z, b.w};
        float cv[4] = {c.x, c.y, c.z, c.w};
#pragma unroll
        for (int j = 0; j < 4; j++) {
            const int ch = c0 + j;
            float w0 = cw[ch * 3 + 0];
            float w1 = cw[ch * 3 + 1];
            float w2 = cw[ch * 3 + 2];
            float v = w0 * av[j] + w1 * bv[j] + w2 * cv[j] + cb[ch];
            float gg = v / (1.0f + expf(-v));   // SiLU
            g[k * 4 + j] = gg;
            amax = fmaxf(amax, fabsf(gg));
        }
    }

    __shared__ float sm[256];
    sm[t] = amax;
    __syncthreads();
    for (int o = 128; o > 0; o >>= 1) {
        if (t < o) sm[t] = fmaxf(sm[t], sm[t + o]);
        __syncthreads();
    }
    const float mx = fmaxf(sm[0], 1e-5f);
    const float scale = 127.0f / mx;
#pragma unroll
    for (int k = 0; k < 4; k++) {
        g_gq[row * (DH/4) + t * 4 + k] =
            pack4(q8(g[k * 4 + 0], scale, -128, 127), q8(g[k * 4 + 1], scale, -128, 127),
                  q8(g[k * 4 + 2], scale, -128, 127), q8(g[k * 4 + 3], scale, -128, 127));
    }
    if (t == 0) g_factg[row] = 1.0f / scale;
}

// ---------------- launch ----------------
extern "C" void kernel_launch(void* const* d_in, const int* in_sizes, int n_in,
                              void* d_out, int out_size) {
    const float* x  = (const float*)d_in[0];
    const float* w1 = (const float*)d_in[1];
    const float* cw = (const float*)d_in[2];
    const float* cb = (const float*)d_in[3];
    const float* w2 = (const float*)d_in[4];
    float* out = (float*)d_out;

    void *p_xq, *p_gq, *p_w1q, *p_w2q, *p_h, *p_fx, *p_fg, *p_ws;
    cudaGetSymbolAddress(&p_xq,  g_xq);
    cudaGetSymbolAddress(&p_gq,  g_gq);
    cudaGetSymbolAddress(&p_w1q, g_w1q);
    cudaGetSymbolAddress(&p_w2q, g_w2q);
    cudaGetSymbolAddress(&p_h,   g_h);
    cudaGetSymbolAddress(&p_fx,  g_factx);
    cudaGetSymbolAddress(&p_fg,  g_factg);
    cudaGetSymbolAddress(&p_ws,  g_wstats);

    // 1. weight stats (deterministic)
    k_wabs_part<<<512, 256>>>(w1, w2);
    k_wabs_final<<<2, 256>>>();

    // 2. quantize activations and weights
    k_quant_x<<<MROWS, 256>>>(x);
    k_quant_w<<<(DH * DM / 4 + 255) / 256, 256>>>(w1, (int*)p_w1q, DH * DM / 4, 0);
    k_quant_w<<<(DM * DH / 4 + 255) / 256, 256>>>(w2, (int*)p_w2q, DM * DH / 4, 2);

    // 3. GEMM1: h = xq @ w1q^T   [8192 x 4096], K=1024
    k_gemm<<<dim3(DH / 128, MROWS / 128), 256>>>(
        (const int*)p_xq, (const int*)p_w1q, (float*)p_h,
        (const float*)p_fx, (const float*)p_ws + 1, DH, DM / 4);

    // 4. depthwise conv3 + SiLU + quantize
    k_conv<<<MROWS, 256>>>(cw, cb);

    // 5. GEMM2: out = gq @ w2q^T  [8192 x 1024], K=4096
    k_gemm<<<dim3(DM / 128, MROWS / 128), 256>>>(
        (const int*)p_gq, (const int*)p_w2q, out,
        (const float*)p_fg, (const float*)p_ws + 3, DM, DH / 4);
}

// round 6
// speedup vs baseline: 1.0568x; 1.0568x over previous
#include <cuda_runtime.h>
#include <math.h>
#include <stdint.h>

// Problem dims (fixed by reference)
#define BB   4
#define SS   2048
#define DM   1024          // d_model
#define DH   4096          // d_hidden
#define MROWS (BB*SS)      // 8192 tokens

// ---------------- static device scratch (no allocation allowed) ----------------
__device__ float  g_h[(size_t)MROWS * DH];        // GEMM1 output (fp32), 128 MB
__device__ int    g_xq[MROWS * (DM/4)];           // x int8 packed, 8 MB
__device__ int    g_gq[MROWS * (DH/4)];           // silu(conv) int8 packed, 32 MB
__device__ int    g_w1q[DH * (DM/4)];             // ternary w1 packed, 4 MB
__device__ int    g_w2q[DM * (DH/4)];             // ternary w2 packed, 4 MB
__device__ float  g_factx[MROWS];                 // per-token 1/scale for x
__device__ float  g_factg[MROWS];                 // per-token 1/scale for g
__device__ double g_part[512];                    // weight |.| partial sums
__device__ float  g_wstats[4];                    // [0]=scale1 [1]=1/scale1 [2]=scale2 [3]=1/scale2

// ---------------- helpers ----------------
__device__ __forceinline__ int pack4(int a, int b, int c, int d) {
    return (a & 0xFF) | ((b & 0xFF) << 8) | ((c & 0xFF) << 16) | ((d & 0xFF) << 24);
}
__device__ __forceinline__ int q8(float v, float s, int lo, int hi) {
    int q = (int)rintf(v * s);
    return min(hi, max(lo, q));
}

// ---------------- weight abs-mean: deterministic 2-stage fp64 reduction ----------------
__global__ void k_wabs_part(const float* __restrict__ w1, const float* __restrict__ w2) {
    const float* w = (blockIdx.x < 256) ? w1 : w2;
    const int b = blockIdx.x & 255;
    const int n = DH * DM;
    const int chunk = n / 256;
    const int base = b * chunk;
    double s = 0.0;
    for (int j = threadIdx.x; j < chunk; j += 256) s += (double)fabsf(w[base + j]);
    __shared__ double sm[256];
    sm[threadIdx.x] = s;
    __syncthreads();
    for (int o = 128; o > 0; o >>= 1) {
        if (threadIdx.x < o) sm[threadIdx.x] += sm[threadIdx.x + o];
        __syncthreads();
    }
    if (threadIdx.x == 0) g_part[blockIdx.x] = sm[0];
}

__global__ void k_wabs_final() {
    const int w = blockIdx.x;  // 0 or 1
    __shared__ double sm[256];
    sm[threadIdx.x] = g_part[w * 256 + threadIdx.x];
    __syncthreads();
    for (int o = 128; o > 0; o >>= 1) {
        if (threadIdx.x < o) sm[threadIdx.x] += sm[threadIdx.x + o];
        __syncthreads();
    }
    if (threadIdx.x == 0) {
        float mean  = (float)(sm[0] / (double)(DH * DM));
        float clipd = fmaxf(mean, 1e-5f);
        float scale = 1.0f / clipd;
        g_wstats[2 * w]     = scale;
        g_wstats[2 * w + 1] = 1.0f / scale;
    }
}

// ---------------- ternary-quantize weights (packed int8) ----------------
__global__ void k_quant_w(const float* __restrict__ w, int* __restrict__ q, int n4, int sidx) {
    const float scale = g_wstats[sidx];
    int i = blockIdx.x * blockDim.x + threadIdx.x;
    if (i < n4) {
        float4 v = reinterpret_cast<const float4*>(w)[i];
        q[i] = pack4(q8(v.x, scale, -1, 1), q8(v.y, scale, -1, 1),
                     q8(v.z, scale, -1, 1), q8(v.w, scale, -1, 1));
    }
}

// ---------------- per-token int8 quantize of x ----------------
__global__ void k_quant_x(const float* __restrict__ x) {
    const int row = blockIdx.x;
    const int t = threadIdx.x;
    float4 v = reinterpret_cast<const float4*>(x + (size_t)row * DM)[t];
    float m = fmaxf(fmaxf(fabsf(v.x), fabsf(v.y)), fmaxf(fabsf(v.z), fabsf(v.w)));
    __shared__ float sm[256];
    sm[t] = m;
    __syncthreads();
    for (int o = 128; o > 0; o >>= 1) {
        if (t < o) sm[t] = fmaxf(sm[t], sm[t + o]);
        __syncthreads();
    }
    float mx = fmaxf(sm[0], 1e-5f);
    float scale = 127.0f / mx;
    g_xq[row * (DM/4) + t] = pack4(q8(v.x, scale, -128, 127), q8(v.y, scale, -128, 127),
                                   q8(v.z, scale, -128, 127), q8(v.w, scale, -128, 127));
    if (t == 0) g_factx[row] = 1.0f / scale;
}

// ---------------- int8 tensor-core GEMM (mma.sync m16n8k32) ----------------
// C[m,n] = (Sum_k A8[m,k]*B8[n,k]) * rowf[m] * ws
// Block tile 128x128, K-slab 64 bytes (16 words). 8 warps, each 64x32.
// Smem rows padded to 20 words (80B): fragment reads are bank-conflict-free.
#define SROW 20

__device__ __forceinline__ void mma_s8(int* c, const int* a, int b0, int b1) {
    asm volatile(
        "mma.sync.aligned.m16n8k32.row.col.s32.s8.s8.s32 "
        "{%0,%1,%2,%3}, {%4,%5,%6,%7}, {%8,%9}, {%0,%1,%2,%3};\n"
        : "+r"(c[0]), "+r"(c[1]), "+r"(c[2]), "+r"(c[3])
        : "r"(a[0]), "r"(a[1]), "r"(a[2]), "r"(a[3]), "r"(b0), "r"(b1));
}

__global__ __launch_bounds__(256, 2)
void k_gemm_imma(const int* __restrict__ A, const int* __restrict__ Bw,
                 float* __restrict__ C, const float* __restrict__ rowf,
                 const float* __restrict__ wsp, int N, int K4) {
    __shared__ int As[2][128 * SROW];
    __shared__ int Bs[2][128 * SROW];
    const int tid  = threadIdx.x;
    const int wid  = tid >> 5;
    const int lane = tid & 31;
    const int warp_m = wid >> 2;       // 0..1  -> 64-row slab
    const int warp_n = wid & 3;        // 0..3  -> 32-col slab
    const int group = lane >> 2;       // 0..7
    const int tcol  = lane & 3;        // 0..3
    const int bm0 = blockIdx.y << 7;
    const int bn0 = blockIdx.x << 7;
    const int T = K4 >> 4;

    const int lc = tid & 15;           // word in k-slab
    const int lr = tid >> 4;           // row base (stride 16)

    int aR[8], bR[8];
    int acc[4][4][4];
#pragma unroll
    for (int mi = 0; mi < 4; mi++)
#pragma unroll
        for (int ni = 0; ni < 4; ni++)
#pragma unroll
            for (int r = 0; r < 4; r++) acc[mi][ni][r] = 0;

    // prefetch k-slab 0
#pragma unroll
    for (int i = 0; i < 8; i++) {
        int r = lr + 16 * i;
        aR[i] = A[(size_t)(bm0 + r) * K4 + lc];
        bR[i] = Bw[(size_t)(bn0 + r) * K4 + lc];
    }

    for (int t = 0; t < T; t++) {
        const int buf = t & 1;
#pragma unroll
        for (int i = 0; i < 8; i++) {
            int r = lr + 16 * i;
            As[buf][r * SROW + lc] = aR[i];
            Bs[buf][r * SROW + lc] = bR[i];
        }
        __syncthreads();
        if (t + 1 < T) {
            const int k0 = (t + 1) << 4;
#pragma unroll
            for (int i = 0; i < 8; i++) {
                int r = lr + 16 * i;
                aR[i] = A[(size_t)(bm0 + r) * K4 + k0 + lc];
                bR[i] = Bw[(size_t)(bn0 + r) * K4 + k0 + lc];
            }
        }
        // two k32 steps per 64B slab
#pragma unroll
        for (int s = 0; s < 2; s++) {
            int afr[4][4];
#pragma unroll
            for (int mi = 0; mi < 4; mi++) {
                const int row = warp_m * 64 + mi * 16 + group;
                const int* p  = &As[buf][row * SROW + s * 8 + tcol];
                afr[mi][0] = p[0];
                afr[mi][2] = p[4];
                afr[mi][1] = p[8 * SROW];
                afr[mi][3] = p[8 * SROW + 4];
            }
#pragma unroll
            for (int ni = 0; ni < 4; ni++) {
                const int col = warp_n * 32 + ni * 8 + group;
                const int* p  = &Bs[buf][col * SROW + s * 8 + tcol];
                const int b0 = p[0];
                const int b1 = p[4];
#pragma unroll
                for (int mi = 0; mi < 4; mi++)
                    mma_s8(acc[mi][ni], afr[mi], b0, b1);
            }
        }
        __syncthreads();
    }

    // epilogue: scale by rowf[m]*ws, write float2 (c0,c1 are adjacent cols)
    const float ws = wsp[0];
#pragma unroll
    for (int mi = 0; mi < 4; mi++) {
        const int r0 = bm0 + warp_m * 64 + mi * 16 + group;
        const float f0 = rowf[r0] * ws;
        const float f1 = rowf[r0 + 8] * ws;
#pragma unroll
        for (int ni = 0; ni < 4; ni++) {
            const int gc = bn0 + warp_n * 32 + ni * 8 + tcol * 2;
            float2 v0 = make_float2((float)acc[mi][ni][0] * f0, (float)acc[mi][ni][1] * f0);
            float2 v1 = make_float2((float)acc[mi][ni][2] * f1, (float)acc[mi][ni][3] * f1);
            *reinterpret_cast<float2*>(&C[(size_t)r0 * N + gc])       = v0;
            *reinterpret_cast<float2*>(&C[(size_t)(r0 + 8) * N + gc]) = v1;
        }
    }
}

// ---------------- depthwise conv3 + bias + SiLU + per-token int8 quantize ----------------
__global__ void k_conv(const float* __restrict__ cw, const float* __restrict__ cb) {
    const int row = blockIdx.x;
    const int s = row & (SS - 1);
    const int t = threadIdx.x;
    const float* h0 = g_h + (size_t)row * DH;
    const float* hm = h0 - DH;
    const float* hp = h0 + DH;
    const bool has_m = (s > 0);
    const bool has_p = (s < SS - 1);

    float g[16];
    float amax = 0.0f;
    const int cbase = t * 16;
#pragma unroll
    for (int k = 0; k < 4; k++) {
        const int c0 = cbase + k * 4;
        float4 a = has_m ? reinterpret_cast<const float4*>(hm + c0)[0] : make_float4(0.f, 0.f, 0.f, 0.f);
        float4 b = reinterpret_cast<const float4*>(h0 + c0)[0];
        float4 c = has_p ? reinterpret_cast<const float4*>(hp + c0)[0] : make_float4(0.f, 0.f, 0.f, 0.f);
        float av[4] = {a.x, a.y, a.z, a.w};
        float bv[4] = {b.x, b.y, b.z, b.w};
        float cv[4] = {c.x, c.y, c.z, c.w};
#pragma unroll
        for (int j = 0; j < 4; j++) {
            const int ch = c0 + j;
            float w0 = cw[ch * 3 + 0];
            float w1 = cw[ch * 3 + 1];
            float w2 = cw[ch * 3 + 2];
            float v = w0 * av[j] + w1 * bv[j] + w2 * cv[j] + cb[ch];
            float gg = v / (1.0f + expf(-v));   // SiLU
            g[k * 4 + j] = gg;
            amax = fmaxf(amax, fabsf(gg));
        }
    }

    __shared__ float sm[256];
    sm[t] = amax;
    __syncthreads();
    for (int o = 128; o > 0; o >>= 1) {
        if (t < o) sm[t] = fmaxf(sm[t], sm[t + o]);
        __syncthreads();
    }
    const float mx = fmaxf(sm[0], 1e-5f);
    const float scale = 127.0f / mx;
#pragma unroll
    for (int k = 0; k < 4; k++) {
        g_gq[row * (DH/4) + t * 4 + k] =
            pack4(q8(g[k * 4 + 0], scale, -128, 127), q8(g[k * 4 + 1], scale, -128, 127),
                  q8(g[k * 4 + 2], scale, -128, 127), q8(g[k * 4 + 3], scale, -128, 127));
    }
    if (t == 0) g_factg[row] = 1.0f / scale;
}

// ---------------- launch ----------------
extern "C" void kernel_launch(void* const* d_in, const int* in_sizes, int n_in,
                              void* d_out, int out_size) {
    const float* x  = (const float*)d_in[0];
    const float* w1 = (const float*)d_in[1];
    const float* cw = (const float*)d_in[2];
    const float* cb = (const float*)d_in[3];
    const float* w2 = (const float*)d_in[4];
    float* out = (float*)d_out;

    void *p_xq, *p_gq, *p_w1q, *p_w2q, *p_h, *p_fx, *p_fg, *p_ws;
    cudaGetSymbolAddress(&p_xq,  g_xq);
    cudaGetSymbolAddress(&p_gq,  g_gq);
    cudaGetSymbolAddress(&p_w1q, g_w1q);
    cudaGetSymbolAddress(&p_w2q, g_w2q);
    cudaGetSymbolAddress(&p_h,   g_h);
    cudaGetSymbolAddress(&p_fx,  g_factx);
    cudaGetSymbolAddress(&p_fg,  g_factg);
    cudaGetSymbolAddress(&p_ws,  g_wstats);

    // 1. weight stats (deterministic)
    k_wabs_part<<<512, 256>>>(w1, w2);
    k_wabs_final<<<2, 256>>>();

    // 2. quantize activations and weights
    k_quant_x<<<MROWS, 256>>>(x);
    k_quant_w<<<(DH * DM / 4 + 255) / 256, 256>>>(w1, (int*)p_w1q, DH * DM / 4, 0);
    k_quant_w<<<(DM * DH / 4 + 255) / 256, 256>>>(w2, (int*)p_w2q, DM * DH / 4, 2);

    // 3. GEMM1: h = xq @ w1q^T   [8192 x 4096], K=1024
    k_gemm_imma<<<dim3(DH / 128, MROWS / 128), 256>>>(
        (const int*)p_xq, (const int*)p_w1q, (float*)p_h,
        (const float*)p_fx, (const float*)p_ws + 1, DH, DM / 4);

    // 4. depthwise conv3 + SiLU + quantize
    k_conv<<<MROWS, 256>>>(cw, cb);

    // 5. GEMM2: out = gq @ w2q^T  [8192 x 1024], K=4096
    k_gemm_imma<<<dim3(DM / 128, MROWS / 128), 256>>>(
        (const int*)p_gq, (const int*)p_w2q, out,
        (const float*)p_fg, (const float*)p_ws + 3, DM, DH / 4);
}

// round 9
// speedup vs baseline: 1.1008x; 1.0416x over previous
#include <cuda_runtime.h>
#include <math.h>
#include <stdint.h>

// Problem dims (fixed by reference)
#define BB   4
#define SS   2048
#define DM   1024          // d_model
#define DH   4096          // d_hidden
#define MROWS (BB*SS)      // 8192 tokens

// ---------------- static device scratch (no allocation allowed) ----------------
__device__ float  g_h[(size_t)MROWS * DH];        // GEMM1 output (fp32), 128 MB
__device__ int    g_xq[MROWS * (DM/4)];           // x int8 packed, 8 MB
__device__ int    g_gq[MROWS * (DH/4)];           // silu(conv) int8 packed, 32 MB
__device__ int    g_w1q[DH * (DM/4)];             // ternary w1 packed, 4 MB
__device__ int    g_w2q[DM * (DH/4)];             // ternary w2 packed, 4 MB
__device__ float  g_factx[MROWS];                 // per-token 1/scale for x
__device__ float  g_factg[MROWS];                 // per-token 1/scale for g
__device__ double g_part[512];                    // weight |.| partial sums
__device__ float  g_wstats[4];                    // [0]=scale1 [1]=1/scale1 [2]=scale2 [3]=1/scale2

// ---------------- helpers ----------------
__device__ __forceinline__ int pack4(int a, int b, int c, int d) {
    return (a & 0xFF) | ((b & 0xFF) << 8) | ((c & 0xFF) << 16) | ((d & 0xFF) << 24);
}
__device__ __forceinline__ int q8(float v, float s, int lo, int hi) {
    int q = (int)rintf(v * s);
    return min(hi, max(lo, q));
}
__device__ __forceinline__ uint32_t smem_u32(const void* p) {
    uint32_t a;
    asm("{ .reg .u64 t; cvta.to.shared.u64 t, %1; cvt.u32.u64 %0, t; }" : "=r"(a) : "l"(p));
    return a;
}
#define CP16(dst, src) asm volatile("cp.async.cg.shared.global [%0], [%1], 16;" :: "r"(dst), "l"(src))
#define CP_COMMIT()    asm volatile("cp.async.commit_group;" ::: "memory")
#define CP_WAIT(n)     asm volatile("cp.async.wait_group %0;" :: "n"(n) : "memory")

__device__ __forceinline__ void ldsm_x4(uint32_t& r0, uint32_t& r1, uint32_t& r2, uint32_t& r3,
                                        uint32_t addr) {
    asm volatile("ldmatrix.sync.aligned.m8n8.x4.shared.b16 {%0,%1,%2,%3}, [%4];"
                 : "=r"(r0), "=r"(r1), "=r"(r2), "=r"(r3) : "r"(addr));
}
__device__ __forceinline__ void mma_s8(int* c, const uint32_t* a, uint32_t b0, uint32_t b1) {
    asm volatile(
        "mma.sync.aligned.m16n8k32.row.col.s32.s8.s8.s32 "
        "{%0,%1,%2,%3}, {%4,%5,%6,%7}, {%8,%9}, {%0,%1,%2,%3};\n"
        : "+r"(c[0]), "+r"(c[1]), "+r"(c[2]), "+r"(c[3])
        : "r"(a[0]), "r"(a[1]), "r"(a[2]), "r"(a[3]), "r"(b0), "r"(b1));
}

// ---------------- weight abs-mean: deterministic 2-stage fp64 reduction ----------------
__global__ void k_wabs_part(const float* __restrict__ w1, const float* __restrict__ w2) {
    const float* w = (blockIdx.x < 256) ? w1 : w2;
    const int b = blockIdx.x & 255;
    const int chunk = (DH * DM) / 256;
    const int base = b * chunk;
    double s = 0.0;
    for (int j = threadIdx.x; j < chunk; j += 256) s += (double)fabsf(w[base + j]);
    __shared__ double sm[256];
    sm[threadIdx.x] = s;
    __syncthreads();
    for (int o = 128; o > 0; o >>= 1) {
        if (threadIdx.x < o) sm[threadIdx.x] += sm[threadIdx.x + o];
        __syncthreads();
    }
    if (threadIdx.x == 0) g_part[blockIdx.x] = sm[0];
}

__global__ void k_wabs_final() {
    const int w = blockIdx.x;  // 0 or 1
    __shared__ double sm[256];
    sm[threadIdx.x] = g_part[w * 256 + threadIdx.x];
    __syncthreads();
    for (int o = 128; o > 0; o >>= 1) {
        if (threadIdx.x < o) sm[threadIdx.x] += sm[threadIdx.x + o];
        __syncthreads();
    }
    if (threadIdx.x == 0) {
        float mean  = (float)(sm[0] / (double)(DH * DM));
        float scale = 1.0f / fmaxf(mean, 1e-5f);
        g_wstats[2 * w]     = scale;
        g_wstats[2 * w + 1] = 1.0f / scale;
    }
}

// ---------------- ternary-quantize weights (packed int8) ----------------
__global__ void k_quant_w(const float* __restrict__ w, int* __restrict__ q, int n4, int sidx) {
    const float scale = g_wstats[sidx];
    int i = blockIdx.x * blockDim.x + threadIdx.x;
    if (i < n4) {
        float4 v = reinterpret_cast<const float4*>(w)[i];
        q[i] = pack4(q8(v.x, scale, -1, 1), q8(v.y, scale, -1, 1),
                     q8(v.z, scale, -1, 1), q8(v.w, scale, -1, 1));
    }
}

// ---------------- per-token int8 quantize of x ----------------
__global__ void k_quant_x(const float* __restrict__ x) {
    const int row = blockIdx.x;
    const int t = threadIdx.x;
    float4 v = reinterpret_cast<const float4*>(x + (size_t)row * DM)[t];
    float m = fmaxf(fmaxf(fabsf(v.x), fabsf(v.y)), fmaxf(fabsf(v.z), fabsf(v.w)));
    __shared__ float sm[256];
    sm[t] = m;
    __syncthreads();
    for (int o = 128; o > 0; o >>= 1) {
        if (t < o) sm[t] = fmaxf(sm[t], sm[t + o]);
        __syncthreads();
    }
    float mx = fmaxf(sm[0], 1e-5f);
    float scale = 127.0f / mx;
    g_xq[row * (DM/4) + t] = pack4(q8(v.x, scale, -128, 127), q8(v.y, scale, -128, 127),
                                   q8(v.z, scale, -128, 127), q8(v.w, scale, -128, 127));
    if (t == 0) g_factx[row] = 1.0f / scale;
}

// ---------------- int8 tensor-core GEMM (ldmatrix + mma.sync + cp.async) ----------------
// C[m,n] = (Sum_k A8[m,k]*B8[n,k]) * rowf[m] * ws
// Block 128x128, K-slab 64 bytes, 2-stage cp.async pipeline.
// Smem rows have 80B stride: rows 0..7 give a full permutation of 16B bank
// groups mod 128 -> ldmatrix is conflict-free.
#define RSTR  80
#define ATILE (128 * RSTR)      // 10240 B
#define STAGE (2 * ATILE)       // A then B, 20480 B

__global__ __launch_bounds__(256, 2)
void k_gemm_imma2(const int8_t* __restrict__ A, const int8_t* __restrict__ Bw,
                  float* __restrict__ C, const float* __restrict__ rowf,
                  const float* __restrict__ wsp, int N, int K) {
    __shared__ int8_t smem[2 * STAGE];   // 40 KB static
    const uint32_t sb = smem_u32(smem);
    const int tid  = threadIdx.x;
    const int wid  = tid >> 5;
    const int lane = tid & 31;
    const int warp_m = wid >> 2;       // 0..1  -> 64-row slab
    const int warp_n = wid & 3;        // 0..3  -> 32-col slab
    const int group = lane >> 2;       // 0..7
    const int tcol  = lane & 3;        // 0..3
    const int bm0 = blockIdx.y << 7;
    const int bn0 = blockIdx.x << 7;
    const int T = K >> 6;              // 64B k-slabs

    // cp.async coords: idx in [0,512): row = idx>>2, 16B chunk = idx&3
    const int r0c = tid >> 2,         c0c = tid & 3;
    const int r1c = (tid + 256) >> 2, c1c = tid & 3;
    const int8_t* Arow0 = A  + (size_t)(bm0 + r0c) * K + c0c * 16;
    const int8_t* Arow1 = A  + (size_t)(bm0 + r1c) * K + c1c * 16;
    const int8_t* Brow0 = Bw + (size_t)(bn0 + r0c) * K + c0c * 16;
    const int8_t* Brow1 = Bw + (size_t)(bn0 + r1c) * K + c1c * 16;
    const uint32_t dA0 = r0c * RSTR + c0c * 16;
    const uint32_t dA1 = r1c * RSTR + c1c * 16;

    // ldmatrix per-thread base offsets within a tile
    const uint32_t a_off = (uint32_t)(warp_m * 64 + (lane & 15)) * RSTR + (lane >> 4) * 16;
    const uint32_t b_off = (uint32_t)(warp_n * 32 + (lane & 15)) * RSTR + (lane >> 4) * 16;

    int acc[4][4][4];
#pragma unroll
    for (int mi = 0; mi < 4; mi++)
#pragma unroll
        for (int ni = 0; ni < 4; ni++)
#pragma unroll
            for (int r = 0; r < 4; r++) acc[mi][ni][r] = 0;

    // prologue: slab 0 -> buf 0
    CP16(sb + dA0,         Arow0);
    CP16(sb + dA1,         Arow1);
    CP16(sb + ATILE + dA0, Brow0);
    CP16(sb + ATILE + dA1, Brow1);
    CP_COMMIT();

    for (int t = 0; t < T; t++) {
        if (t + 1 < T) {
            const uint32_t sd = sb + ((t + 1) & 1) * STAGE;
            const int kk = (t + 1) << 6;
            CP16(sd + dA0,         Arow0 + kk);
            CP16(sd + dA1,         Arow1 + kk);
            CP16(sd + ATILE + dA0, Brow0 + kk);
            CP16(sd + ATILE + dA1, Brow1 + kk);
            CP_COMMIT();
            CP_WAIT(1);          // slab t now resident
        } else {
            CP_WAIT(0);
        }
        __syncthreads();

        const uint32_t abase = sb + (t & 1) * STAGE + a_off;
        const uint32_t bbase = sb + (t & 1) * STAGE + ATILE + b_off;
#pragma unroll
        for (int s = 0; s < 2; s++) {
            uint32_t afr[4][4];
#pragma unroll
            for (int mi = 0; mi < 4; mi++)
                ldsm_x4(afr[mi][0], afr[mi][1], afr[mi][2], afr[mi][3],
                        abase + mi * 16 * RSTR + s * 32);
            uint32_t bfr[4][2];
#pragma unroll
            for (int pi = 0; pi < 2; pi++) {
                uint32_t q0, q1, q2, q3;
                ldsm_x4(q0, q1, q2, q3, bbase + pi * 16 * RSTR + s * 32);
                bfr[2 * pi][0]     = q0;  bfr[2 * pi][1]     = q2;
                bfr[2 * pi + 1][0] = q1;  bfr[2 * pi + 1][1] = q3;
            }
#pragma unroll
            for (int ni = 0; ni < 4; ni++)
#pragma unroll
                for (int mi = 0; mi < 4; mi++)
                    mma_s8(acc[mi][ni], afr[mi], bfr[ni][0], bfr[ni][1]);
        }
        __syncthreads();
    }

    // epilogue: scale by rowf[m]*ws
    const float ws = wsp[0];
#pragma unroll
    for (int mi = 0; mi < 4; mi++) {
        const int r0 = bm0 + warp_m * 64 + mi * 16 + group;
        const float f0 = rowf[r0] * ws;
        const float f1 = rowf[r0 + 8] * ws;
#pragma unroll
        for (int ni = 0; ni < 4; ni++) {
            const int gc = bn0 + warp_n * 32 + ni * 8 + tcol * 2;
            float2 v0 = make_float2((float)acc[mi][ni][0] * f0, (float)acc[mi][ni][1] * f0);
            float2 v1 = make_float2((float)acc[mi][ni][2] * f1, (float)acc[mi][ni][3] * f1);
            *reinterpret_cast<float2*>(&C[(size_t)r0 * N + gc])       = v0;
            *reinterpret_cast<float2*>(&C[(size_t)(r0 + 8) * N + gc]) = v1;
        }
    }
}

// ---------------- depthwise conv3 + bias + SiLU + per-token int8 quantize ----------------
__global__ void k_conv(const float* __restrict__ cw, const float* __restrict__ cb) {
    const int row = blockIdx.x;
    const int s = row & (SS - 1);
    const int t = threadIdx.x;
    const float* h0 = g_h + (size_t)row * DH;
    const float* hm = h0 - DH;
    const float* hp = h0 + DH;
    const bool has_m = (s > 0);
    const bool has_p = (s < SS - 1);

    float g[16];
    float amax = 0.0f;
    const int cbase = t * 16;
#pragma unroll
    for (int k = 0; k < 4; k++) {
        const int c0 = cbase + k * 4;
        float4 a = has_m ? reinterpret_cast<const float4*>(hm + c0)[0] : make_float4(0.f, 0.f, 0.f, 0.f);
        float4 b = reinterpret_cast<const float4*>(h0 + c0)[0];
        float4 c = has_p ? reinterpret_cast<const float4*>(hp + c0)[0] : make_float4(0.f, 0.f, 0.f, 0.f);
        float av[4] = {a.x, a.y, a.z, a.w};
        float bv[4] = {b.x, b.y, b.z, b.w};
        float cv[4] = {c.x, c.y, c.z, c.w};
#pragma unroll
        for (int j = 0; j < 4; j++) {
            const int ch = c0 + j;
            float w0 = cw[ch * 3 + 0];
            float w1 = cw[ch * 3 + 1];
            float w2 = cw[ch * 3 + 2];
            float v = w0 * av[j] + w1 * bv[j] + w2 * cv[j] + cb[ch];
            float gg = v / (1.0f + expf(-v));   // SiLU
            g[k * 4 + j] = gg;
            amax = fmaxf(amax, fabsf(gg));
        }
    }

    __shared__ float sm[256];
    sm[t] = amax;
    __syncthreads();
    for (int o = 128; o > 0; o >>= 1) {
        if (t < o) sm[t] = fmaxf(sm[t], sm[t + o]);
        __syncthreads();
    }
    const float mx = fmaxf(sm[0], 1e-5f);
    const float scale = 127.0f / mx;
#pragma unroll
    for (int k = 0; k < 4; k++) {
        g_gq[row * (DH/4) + t * 4 + k] =
            pack4(q8(g[k * 4 + 0], scale, -128, 127), q8(g[k * 4 + 1], scale, -128, 127),
                  q8(g[k * 4 + 2], scale, -128, 127), q8(g[k * 4 + 3], scale, -128, 127));
    }
    if (t == 0) g_factg[row] = 1.0f / scale;
}

// ---------------- launch ----------------
extern "C" void kernel_launch(void* const* d_in, const int* in_sizes, int n_in,
                              void* d_out, int out_size) {
    const float* x  = (const float*)d_in[0];
    const float* w1 = (const float*)d_in[1];
    const float* cw = (const float*)d_in[2];
    const float* cb = (const float*)d_in[3];
    const float* w2 = (const float*)d_in[4];
    float* out = (float*)d_out;

    void *p_xq, *p_gq, *p_w1q, *p_w2q, *p_h, *p_fx, *p_fg, *p_ws;
    cudaGetSymbolAddress(&p_xq,  g_xq);
    cudaGetSymbolAddress(&p_gq,  g_gq);
    cudaGetSymbolAddress(&p_w1q, g_w1q);
    cudaGetSymbolAddress(&p_w2q, g_w2q);
    cudaGetSymbolAddress(&p_h,   g_h);
    cudaGetSymbolAddress(&p_fx,  g_factx);
    cudaGetSymbolAddress(&p_fg,  g_factg);
    cudaGetSymbolAddress(&p_ws,  g_wstats);

    // 1. weight stats (deterministic)
    k_wabs_part<<<512, 256>>>(w1, w2);
    k_wabs_final<<<2, 256>>>();

    // 2. quantize activations and weights
    k_quant_x<<<MROWS, 256>>>(x);
    k_quant_w<<<(DH * DM / 4 + 255) / 256, 256>>>(w1, (int*)p_w1q, DH * DM / 4, 0);
    k_quant_w<<<(DM * DH / 4 + 255) / 256, 256>>>(w2, (int*)p_w2q, DM * DH / 4, 2);

    // 3. GEMM1: h = xq @ w1q^T   [8192 x 4096], K=1024 bytes
    k_gemm_imma2<<<dim3(DH / 128, MROWS / 128), 256>>>(
        (const int8_t*)p_xq, (const int8_t*)p_w1q, (float*)p_h,
        (const float*)p_fx, (const float*)p_ws + 1, DH, DM);

    // 4. depthwise conv3 + SiLU + quantize
    k_conv<<<MROWS, 256>>>(cw, cb);

    // 5. GEMM2: out = gq @ w2q^T  [8192 x 1024], K=4096 bytes
    k_gemm_imma2<<<dim3(DM / 128, MROWS / 128), 256>>>(
        (const int8_t*)p_gq, (const int8_t*)p_w2q, out,
        (const float*)p_fg, (const float*)p_ws + 3, DM, DH);
}

// round 12
// speedup vs baseline: 1.2461x; 1.1320x over previous
#include <cuda_runtime.h>
#include <math.h>
#include <stdint.h>

// Problem dims (fixed by reference)
#define BB   4
#define SS   2048
#define DM   1024          // d_model
#define DH   4096          // d_hidden
#define MROWS (BB*SS)      // 8192 tokens

// ---------------- static device scratch (no allocation allowed) ----------------
__device__ float  g_h[(size_t)MROWS * DH];        // GEMM1 output (fp32), 128 MB
__device__ int    g_xq[MROWS * (DM/4)];           // x int8 packed, 8 MB
__device__ int    g_gq[MROWS * (DH/4)];           // silu(conv) int8 packed, 32 MB
__device__ int    g_w1q[DH * (DM/4)];             // ternary w1 packed, 4 MB
__device__ int    g_w2q[DM * (DH/4)];             // ternary w2 packed, 4 MB
__device__ float  g_factx[MROWS];                 // per-token 1/scale for x
__device__ float  g_factg[MROWS];                 // per-token 1/scale for g
__device__ double g_part[512];                    // weight |.| partial sums
__device__ float  g_wstats[4];                    // [0]=scale1 [1]=1/scale1 [2]=scale2 [3]=1/scale2

// ---------------- helpers ----------------
__device__ __forceinline__ int pack4(int a, int b, int c, int d) {
    return (a & 0xFF) | ((b & 0xFF) << 8) | ((c & 0xFF) << 16) | ((d & 0xFF) << 24);
}
__device__ __forceinline__ int q8(float v, float s, int lo, int hi) {
    int q = (int)rintf(v * s);
    return min(hi, max(lo, q));
}
__device__ __forceinline__ uint32_t smem_u32(const void* p) {
    uint32_t a;
    asm("{ .reg .u64 t; cvta.to.shared.u64 t, %1; cvt.u32.u64 %0, t; }" : "=r"(a) : "l"(p));
    return a;
}
#define CP16(dst, src) asm volatile("cp.async.cg.shared.global [%0], [%1], 16;" :: "r"(dst), "l"(src))
#define CP_COMMIT()    asm volatile("cp.async.commit_group;" ::: "memory")
#define CP_WAIT(n)     asm volatile("cp.async.wait_group %0;" :: "n"(n) : "memory")

__device__ __forceinline__ void ldsm_x4(uint32_t& r0, uint32_t& r1, uint32_t& r2, uint32_t& r3,
                                        uint32_t addr) {
    asm volatile("ldmatrix.sync.aligned.m8n8.x4.shared.b16 {%0,%1,%2,%3}, [%4];"
                 : "=r"(r0), "=r"(r1), "=r"(r2), "=r"(r3) : "r"(addr));
}
__device__ __forceinline__ void mma_s8(int* c, const uint32_t* a, uint32_t b0, uint32_t b1) {
    asm volatile(
        "mma.sync.aligned.m16n8k32.row.col.s32.s8.s8.s32 "
        "{%0,%1,%2,%3}, {%4,%5,%6,%7}, {%8,%9}, {%0,%1,%2,%3};\n"
        : "+r"(c[0]), "+r"(c[1]), "+r"(c[2]), "+r"(c[3])
        : "r"(a[0]), "r"(a[1]), "r"(a[2]), "r"(a[3]), "r"(b0), "r"(b1));
}

// ---------------- weight abs-mean: deterministic 2-stage fp64 reduction ----------------
__global__ void k_wabs_part(const float* __restrict__ w1, const float* __restrict__ w2) {
    const float* w = (blockIdx.x < 256) ? w1 : w2;
    const int b = blockIdx.x & 255;
    const int chunk = (DH * DM) / 256;
    const int base = b * chunk;
    double s = 0.0;
    for (int j = threadIdx.x; j < chunk; j += 256) s += (double)fabsf(w[base + j]);
    __shared__ double sm[256];
    sm[threadIdx.x] = s;
    __syncthreads();
    for (int o = 128; o > 0; o >>= 1) {
        if (threadIdx.x < o) sm[threadIdx.x] += sm[threadIdx.x + o];
        __syncthreads();
    }
    if (threadIdx.x == 0) g_part[blockIdx.x] = sm[0];
}

__global__ void k_wabs_final() {
    const int w = blockIdx.x;  // 0 or 1
    __shared__ double sm[256];
    sm[threadIdx.x] = g_part[w * 256 + threadIdx.x];
    __syncthreads();
    for (int o = 128; o > 0; o >>= 1) {
        if (threadIdx.x < o) sm[threadIdx.x] += sm[threadIdx.x + o];
        __syncthreads();
    }
    if (threadIdx.x == 0) {
        float mean  = (float)(sm[0] / (double)(DH * DM));
        float scale = 1.0f / fmaxf(mean, 1e-5f);
        g_wstats[2 * w]     = scale;
        g_wstats[2 * w + 1] = 1.0f / scale;
    }
}

// ---------------- ternary-quantize BOTH weights in one launch ----------------
// blocks [0,4096) -> w1, [4096,8192) -> w2
__global__ void k_quant_w2x(const float* __restrict__ w1, const float* __restrict__ w2) {
    const bool second = blockIdx.x >= 4096;
    const float* w = second ? w2 : w1;
    int* q = second ? g_w2q : g_w1q;
    const float scale = g_wstats[second ? 2 : 0];
    const int i = (blockIdx.x & 4095) * blockDim.x + threadIdx.x;   // < 1,048,576 = DH*DM/4
    float4 v = reinterpret_cast<const float4*>(w)[i];
    q[i] = pack4(q8(v.x, scale, -1, 1), q8(v.y, scale, -1, 1),
                 q8(v.z, scale, -1, 1), q8(v.w, scale, -1, 1));
}

// ---------------- per-token int8 quantize of x ----------------
__global__ void k_quant_x(const float* __restrict__ x) {
    const int row = blockIdx.x;
    const int t = threadIdx.x;
    float4 v = reinterpret_cast<const float4*>(x + (size_t)row * DM)[t];
    float m = fmaxf(fmaxf(fabsf(v.x), fabsf(v.y)), fmaxf(fabsf(v.z), fabsf(v.w)));
    __shared__ float sm[256];
    sm[t] = m;
    __syncthreads();
    for (int o = 128; o > 0; o >>= 1) {
        if (t < o) sm[t] = fmaxf(sm[t], sm[t + o]);
        __syncthreads();
    }
    float mx = fmaxf(sm[0], 1e-5f);
    float scale = 127.0f / mx;
    g_xq[row * (DM/4) + t] = pack4(q8(v.x, scale, -128, 127), q8(v.y, scale, -128, 127),
                                   q8(v.z, scale, -128, 127), q8(v.w, scale, -128, 127));
    if (t == 0) g_factx[row] = 1.0f / scale;
}

// ---------------- int8 tensor-core GEMM (ldmatrix + mma.sync + cp.async) ----------------
// C[m,n] = (Sum_k A8[m,k]*B8[n,k]) * rowf[m] * ws
// Block 128x128, K-slab 64 bytes, 2-stage cp.async pipeline.
// Smem rows have 80B stride: rows 0..7 give a full permutation of 16B bank
// groups mod 128 -> ldmatrix is conflict-free.
#define RSTR  80
#define ATILE (128 * RSTR)      // 10240 B
#define STAGE (2 * ATILE)       // A then B, 20480 B

__global__ __launch_bounds__(256, 2)
void k_gemm_imma2(const int8_t* __restrict__ A, const int8_t* __restrict__ Bw,
                  float* __restrict__ C, const float* __restrict__ rowf,
                  const float* __restrict__ wsp, int N, int K) {
    __shared__ int8_t smem[2 * STAGE];   // 40 KB static
    const uint32_t sb = smem_u32(smem);
    const int tid  = threadIdx.x;
    const int wid  = tid >> 5;
    const int lane = tid & 31;
    const int warp_m = wid >> 2;       // 0..1  -> 64-row slab
    const int warp_n = wid & 3;        // 0..3  -> 32-col slab
    const int group = lane >> 2;       // 0..7
    const int tcol  = lane & 3;        // 0..3
    const int bm0 = blockIdx.y << 7;
    const int bn0 = blockIdx.x << 7;
    const int T = K >> 6;              // 64B k-slabs

    // cp.async coords: idx in [0,512): row = idx>>2, 16B chunk = idx&3
    const int r0c = tid >> 2,         c0c = tid & 3;
    const int r1c = (tid + 256) >> 2, c1c = tid & 3;
    const int8_t* Arow0 = A  + (size_t)(bm0 + r0c) * K + c0c * 16;
    const int8_t* Arow1 = A  + (size_t)(bm0 + r1c) * K + c1c * 16;
    const int8_t* Brow0 = Bw + (size_t)(bn0 + r0c) * K + c0c * 16;
    const int8_t* Brow1 = Bw + (size_t)(bn0 + r1c) * K + c1c * 16;
    const uint32_t dA0 = r0c * RSTR + c0c * 16;
    const uint32_t dA1 = r1c * RSTR + c1c * 16;

    // ldmatrix per-thread base offsets within a tile
    const uint32_t a_off = (uint32_t)(warp_m * 64 + (lane & 15)) * RSTR + (lane >> 4) * 16;
    const uint32_t b_off = (uint32_t)(warp_n * 32 + (lane & 15)) * RSTR + (lane >> 4) * 16;

    int acc[4][4][4];
#pragma unroll
    for (int mi = 0; mi < 4; mi++)
#pragma unroll
        for (int ni = 0; ni < 4; ni++)
#pragma unroll
            for (int r = 0; r < 4; r++) acc[mi][ni][r] = 0;

    // prologue: slab 0 -> buf 0
    CP16(sb + dA0,         Arow0);
    CP16(sb + dA1,         Arow1);
    CP16(sb + ATILE + dA0, Brow0);
    CP16(sb + ATILE + dA1, Brow1);
    CP_COMMIT();

    for (int t = 0; t < T; t++) {
        if (t + 1 < T) {
            const uint32_t sd = sb + ((t + 1) & 1) * STAGE;
            const int kk = (t + 1) << 6;
            CP16(sd + dA0,         Arow0 + kk);
            CP16(sd + dA1,         Arow1 + kk);
            CP16(sd + ATILE + dA0, Brow0 + kk);
            CP16(sd + ATILE + dA1, Brow1 + kk);
            CP_COMMIT();
            CP_WAIT(1);          // slab t now resident
        } else {
            CP_WAIT(0);
        }
        __syncthreads();

        const uint32_t abase = sb + (t & 1) * STAGE + a_off;
        const uint32_t bbase = sb + (t & 1) * STAGE + ATILE + b_off;
#pragma unroll
        for (int s = 0; s < 2; s++) {
            uint32_t afr[4][4];
#pragma unroll
            for (int mi = 0; mi < 4; mi++)
                ldsm_x4(afr[mi][0], afr[mi][1], afr[mi][2], afr[mi][3],
                        abase + mi * 16 * RSTR + s * 32);
            uint32_t bfr[4][2];
#pragma unroll
            for (int pi = 0; pi < 2; pi++) {
                uint32_t q0, q1, q2, q3;
                ldsm_x4(q0, q1, q2, q3, bbase + pi * 16 * RSTR + s * 32);
                bfr[2 * pi][0]     = q0;  bfr[2 * pi][1]     = q2;
                bfr[2 * pi + 1][0] = q1;  bfr[2 * pi + 1][1] = q3;
            }
#pragma unroll
            for (int ni = 0; ni < 4; ni++)
#pragma unroll
                for (int mi = 0; mi < 4; mi++)
                    mma_s8(acc[mi][ni], afr[mi], bfr[ni][0], bfr[ni][1]);
        }
        __syncthreads();
    }

    // epilogue: scale by rowf[m]*ws
    const float ws = wsp[0];
#pragma unroll
    for (int mi = 0; mi < 4; mi++) {
        const int r0 = bm0 + warp_m * 64 + mi * 16 + group;
        const float f0 = rowf[r0] * ws;
        const float f1 = rowf[r0 + 8] * ws;
#pragma unroll
        for (int ni = 0; ni < 4; ni++) {
            const int gc = bn0 + warp_n * 32 + ni * 8 + tcol * 2;
            float2 v0 = make_float2((float)acc[mi][ni][0] * f0, (float)acc[mi][ni][1] * f0);
            float2 v1 = make_float2((float)acc[mi][ni][2] * f1, (float)acc[mi][ni][3] * f1);
            *reinterpret_cast<float2*>(&C[(size_t)r0 * N + gc])       = v0;
            *reinterpret_cast<float2*>(&C[(size_t)(r0 + 8) * N + gc]) = v1;
        }
    }
}

// ---------------- depthwise conv3 + bias + SiLU + per-token int8 quantize ----------------
// 8-token strips per block: consecutive tokens reuse g_h rows via L1
// (DRAM reads drop from 3x to ~1.25x of g_h). Conv weights hoisted to registers.
// Warp-shuffle amax reduction + parity-buffered smem (1 barrier per token).
#define CONV_T 8

__global__ __launch_bounds__(256)
void k_conv(const float* __restrict__ cw, const float* __restrict__ cb) {
    const int t    = threadIdx.x;
    const int lane = t & 31;
    const int wrp  = t >> 5;
    const int row0 = blockIdx.x * CONV_T;
    const int cbase = t * 16;

    __shared__ float warpmax[2][8];

    // hoist per-thread conv weights (16 channels) into registers
    float rw0[16], rw1[16], rw2[16], rb[16];
#pragma unroll
    for (int j = 0; j < 16; j++) {
        const int ch = cbase + j;
        rw0[j] = cw[ch * 3 + 0];
        rw1[j] = cw[ch * 3 + 1];
        rw2[j] = cw[ch * 3 + 2];
        rb[j]  = cb[ch];
    }

    for (int ti = 0; ti < CONV_T; ti++) {
        const int row = row0 + ti;
        const int s = row & (SS - 1);
        const float* h0 = g_h + (size_t)row * DH;
        const float* hm = h0 - DH;
        const float* hp = h0 + DH;
        const bool has_m = (s > 0);
        const bool has_p = (s < SS - 1);

        float g[16];
        float amax = 0.0f;
#pragma unroll
        for (int k = 0; k < 4; k++) {
            const int c0 = cbase + k * 4;
            float4 a = has_m ? reinterpret_cast<const float4*>(hm + c0)[0] : make_float4(0.f, 0.f, 0.f, 0.f);
            float4 b = reinterpret_cast<const float4*>(h0 + c0)[0];
            float4 c = has_p ? reinterpret_cast<const float4*>(hp + c0)[0] : make_float4(0.f, 0.f, 0.f, 0.f);
            float av[4] = {a.x, a.y, a.z, a.w};
            float bv[4] = {b.x, b.y, b.z, b.w};
            float cv[4] = {c.x, c.y, c.z, c.w};
#pragma unroll
            for (int j = 0; j < 4; j++) {
                const int jj = k * 4 + j;
                float v = rw0[jj] * av[j] + rw1[jj] * bv[j] + rw2[jj] * cv[j] + rb[jj];
                float gg = v / (1.0f + expf(-v));   // SiLU
                g[jj] = gg;
                amax = fmaxf(amax, fabsf(gg));
            }
        }

        // warp-level max reduce
#pragma unroll
        for (int o = 16; o > 0; o >>= 1)
            amax = fmaxf(amax, __shfl_xor_sync(0xFFFFFFFFu, amax, o));
        const int pb = ti & 1;
        if (lane == 0) warpmax[pb][wrp] = amax;
        __syncthreads();
        float mx = warpmax[pb][0];
#pragma unroll
        for (int wv = 1; wv < 8; wv++) mx = fmaxf(mx, warpmax[pb][wv]);
        mx = fmaxf(mx, 1e-5f);
        const float scale = 127.0f / mx;

        int4 outv;
        outv.x = pack4(q8(g[0],  scale, -128, 127), q8(g[1],  scale, -128, 127),
                       q8(g[2],  scale, -128, 127), q8(g[3],  scale, -128, 127));
        outv.y = pack4(q8(g[4],  scale, -128, 127), q8(g[5],  scale, -128, 127),
                       q8(g[6],  scale, -128, 127), q8(g[7],  scale, -128, 127));
        outv.z = pack4(q8(g[8],  scale, -128, 127), q8(g[9],  scale, -128, 127),
                       q8(g[10], scale, -128, 127), q8(g[11], scale, -128, 127));
        outv.w = pack4(q8(g[12], scale, -128, 127), q8(g[13], scale, -128, 127),
                       q8(g[14], scale, -128, 127), q8(g[15], scale, -128, 127));
        *reinterpret_cast<int4*>(&g_gq[row * (DH/4) + t * 4]) = outv;

        if (t == 0) g_factg[row] = 1.0f / scale;
    }
}

// ---------------- launch ----------------
extern "C" void kernel_launch(void* const* d_in, const int* in_sizes, int n_in,
                              void* d_out, int out_size) {
    const float* x  = (const float*)d_in[0];
    const float* w1 = (const float*)d_in[1];
    const float* cw = (const float*)d_in[2];
    const float* cb = (const float*)d_in[3];
    const float* w2 = (const float*)d_in[4];
    float* out = (float*)d_out;

    void *p_xq, *p_gq, *p_w1q, *p_w2q, *p_h, *p_fx, *p_fg, *p_ws;
    cudaGetSymbolAddress(&p_xq,  g_xq);
    cudaGetSymbolAddress(&p_gq,  g_gq);
    cudaGetSymbolAddress(&p_w1q, g_w1q);
    cudaGetSymbolAddress(&p_w2q, g_w2q);
    cudaGetSymbolAddress(&p_h,   g_h);
    cudaGetSymbolAddress(&p_fx,  g_factx);
    cudaGetSymbolAddress(&p_fg,  g_factg);
    cudaGetSymbolAddress(&p_ws,  g_wstats);

    // 1-2. weight stats (deterministic)
    k_wabs_part<<<512, 256>>>(w1, w2);
    k_wabs_final<<<2, 256>>>();

    // 3. quantize activations
    k_quant_x<<<MROWS, 256>>>(x);

    // 4. quantize both weight matrices (single launch)
    k_quant_w2x<<<8192, 256>>>(w1, w2);

    // 5. GEMM1: h = xq @ w1q^T   [8192 x 4096], K=1024 bytes   <-- ncu capture slot
    k_gemm_imma2<<<dim3(DH / 128, MROWS / 128), 256>>>(
        (const int8_t*)p_xq, (const int8_t*)p_w1q, (float*)p_h,
        (const float*)p_fx, (const float*)p_ws + 1, DH, DM);

    // 6. depthwise conv3 + SiLU + quantize (8-token strips)
    k_conv<<<MROWS / CONV_T, 256>>>(cw, cb);

    // 7. GEMM2: out = gq @ w2q^T  [8192 x 1024], K=4096 bytes
    k_gemm_imma2<<<dim3(DM / 128, MROWS / 128), 256>>>(
        (const int8_t*)p_gq, (const int8_t*)p_w2q, out,
        (const float*)p_fg, (const float*)p_ws + 3, DM, DH);
}